// round 1
// baseline (speedup 1.0000x reference)
#include <cuda_runtime.h>
#include <math.h>

#define NN    576
#define MR    144
#define RD    15
#define BATCH 256
#define ITERS 3

// Column indices of the 15 ones in each of the 144 rows of H.
__device__ int g_cols[MR * RD];

// One thread per check row: scan its 576-entry row of H, record the 15 set columns.
__global__ void ldpc_prep_kernel(const float* __restrict__ H) {
    int m = threadIdx.x;
    if (m < MR) {
        int cnt = 0;
        const float* row = H + m * NN;
        for (int n = 0; n < NN; n++) {
            if (row[n] == 1.0f) {
                if (cnt < RD) g_cols[m * RD + cnt] = n;
                cnt++;
            }
        }
    }
}

// One block per batch element, one thread per check row (144 threads).
__global__ __launch_bounds__(MR, 8)
void ldpc_decode_kernel(const float* __restrict__ r,
                        const float* __restrict__ alpha,
                        const float* __restrict__ beta,
                        float* __restrict__ out) {
    __shared__ float V[NN];    // r + column-sum of E (the "posterior")
    __shared__ float rsh[NN];  // cached channel values for this batch element

    const int b = blockIdx.x;
    const int t = threadIdx.x;   // check-row index, 0..143
    const float* rb = r + b * NN;

    // Load r for this batch element; init V = r (so first-iter M = H*r).
    #pragma unroll
    for (int n = t; n < NN; n += MR) {
        float v = rb[n];
        rsh[n] = v;
        V[n]   = v;
    }

    int   cols[RD];
    float Mv[RD];
    float Eprev[RD];
    #pragma unroll
    for (int j = 0; j < RD; j++) {
        cols[j]  = g_cols[t * RD + j];
        Eprev[j] = 0.0f;
    }
    __syncthreads();

    #pragma unroll
    for (int it = 0; it < ITERS; it++) {
        const float a  = alpha[it];
        const float bt = beta[it];

        // --- c-to-v: per row, min1/min2/argmin over |M| and sign product ---
        float min1 = INFINITY, min2 = INFINITY;
        int   jmin = -1;
        float sgn  = 1.0f;
        #pragma unroll
        for (int j = 0; j < RD; j++) {
            float m  = V[cols[j]] - Eprev[j];   // M = r + sumE - E_prev on this edge
            Mv[j] = m;
            float am = fabsf(m);
            float s  = (m > 0.0f) ? 1.0f : ((m < 0.0f) ? -1.0f : 0.0f);
            sgn *= s;
            if (am < min1) { min2 = min1; min1 = am; jmin = j; }
            else if (am < min2) { min2 = am; }
        }
        __syncthreads();           // everyone done reading V

        // Reset V to channel values before accumulating new E.
        #pragma unroll
        for (int n = t; n < NN; n += MR) V[n] = rsh[n];
        __syncthreads();

        // --- emit E and accumulate column sums into V ---
        const float m2mb = fmaxf(0.0f, min2 - bt);
        const float m1mb = fmaxf(0.0f, min1 - bt);
        #pragma unroll
        for (int j = 0; j < RD; j++) {
            float m = Mv[j];
            float s = (m > 0.0f) ? 1.0f : ((m < 0.0f) ? -1.0f : 0.0f);
            float e = a * sgn * s * ((j == jmin) ? m2mb : m1mb);
            Eprev[j] = e;
            atomicAdd(&V[cols[j]], e);
        }
        __syncthreads();           // V now = r + sum_E for this iteration
    }

    // Output = r + sum(E last iter) = V.
    float* ob = out + b * NN;
    #pragma unroll
    for (int n = t; n < NN; n += MR) ob[n] = V[n];
}

extern "C" void kernel_launch(void* const* d_in, const int* in_sizes, int n_in,
                              void* d_out, int out_size) {
    const float* r     = (const float*)d_in[0];   // (256, 576)
    const float* H     = (const float*)d_in[1];   // (144, 576)
    const float* alpha = (const float*)d_in[2];   // (3,)
    const float* beta  = (const float*)d_in[3];   // (3,)
    float* out = (float*)d_out;                   // (256, 576)

    ldpc_prep_kernel<<<1, MR>>>(H);
    ldpc_decode_kernel<<<BATCH, MR>>>(r, alpha, beta, out);
}

// round 2
// speedup vs baseline: 4.2059x; 4.2059x over previous
#include <cuda_runtime.h>
#include <math.h>

#define NN    576
#define MR    144
#define RD    15
#define BATCH 256
#define ITERS 3
#define SUBS  2                 // batch elements per decode block
#define TPB   (MR * SUBS)       // 288 threads

// Column indices of the 15 ones in each of the 144 rows of H.
__device__ int g_cols[MR * RD];

// Warp-per-row prep: ballot-compact the set columns, preserving ascending order.
__global__ void ldpc_prep_kernel(const float* __restrict__ H) {
    const int m    = blockIdx.x;      // check row
    const int lane = threadIdx.x;     // 0..31
    const float* row = H + m * NN;
    int cnt = 0;
    #pragma unroll
    for (int base = 0; base < NN; base += 32) {
        float v = row[base + lane];
        unsigned mask = __ballot_sync(0xFFFFFFFFu, v == 1.0f);
        if (v == 1.0f) {
            int pos = cnt + __popc(mask & ((1u << lane) - 1u));
            g_cols[m * RD + pos] = base + lane;
        }
        cnt += __popc(mask);
    }
}

// One block = SUBS batch elements; within a sub-block, one thread per check row.
__global__ __launch_bounds__(TPB, 1)
void ldpc_decode_kernel(const float* __restrict__ r,
                        const float* __restrict__ alpha,
                        const float* __restrict__ beta,
                        float* __restrict__ out) {
    // V[buf][sub][n]: double-buffered posterior (r + column-sum of E).
    __shared__ float V[2][SUBS][NN];
    __shared__ float rsh[SUBS][NN];

    const int t   = threadIdx.x;
    const int sub = t / MR;           // which batch element in this block
    const int row = t - sub * MR;     // check-row index 0..143
    const int b   = blockIdx.x * SUBS + sub;
    const float* rb = r + b * NN;

    // Hoist all alpha/beta (L2-cached after first block).
    float a_[ITERS], bt_[ITERS];
    #pragma unroll
    for (int it = 0; it < ITERS; it++) { a_[it] = alpha[it]; bt_[it] = beta[it]; }

    // Load r; init both V buffers to r.
    #pragma unroll
    for (int n = row; n < NN; n += MR) {
        float v = rb[n];
        rsh[sub][n]  = v;
        V[0][sub][n] = v;
        V[1][sub][n] = v;
    }

    int   cols[RD];
    float Mv[RD];
    float Eprev[RD];
    #pragma unroll
    for (int j = 0; j < RD; j++) {
        cols[j]  = g_cols[row * RD + j];
        Eprev[j] = 0.0f;
    }
    __syncthreads();

    #pragma unroll
    for (int it = 0; it < ITERS; it++) {
        const int cur = it & 1, nxt = cur ^ 1;
        const float a  = a_[it];
        const float bt = bt_[it];

        // --- c-to-v: min1/min2/argmin over |M| and sign product over the row ---
        float min1 = INFINITY, min2 = INFINITY;
        int   jmin = -1;
        float sgn  = 1.0f;
        #pragma unroll
        for (int j = 0; j < RD; j++) {
            float m  = V[cur][sub][cols[j]] - Eprev[j];  // extrinsic message
            Mv[j] = m;
            float s  = (m > 0.0f) ? 1.0f : ((m < 0.0f) ? -1.0f : 0.0f);
            sgn *= s;
            float am = fabsf(m);
            if (am < min1) { min2 = min1; min1 = am; jmin = j; }
            else if (am < min2) { min2 = am; }
        }

        // --- emit E into the other buffer (already holds r) ---
        const float m2mb = a * sgn * fmaxf(0.0f, min2 - bt);
        const float m1mb = a * sgn * fmaxf(0.0f, min1 - bt);
        #pragma unroll
        for (int j = 0; j < RD; j++) {
            float m = Mv[j];
            float s = (m > 0.0f) ? 1.0f : ((m < 0.0f) ? -1.0f : 0.0f);
            float e = s * ((j == jmin) ? m2mb : m1mb);
            Eprev[j] = e;
            atomicAdd(&V[nxt][sub][cols[j]], e);
        }
        __syncthreads();   // V[nxt] final; all reads of V[cur] done

        if (it < ITERS - 1) {
            // Recycle V[cur] as the next "fresh r" accumulator.
            #pragma unroll
            for (int n = row; n < NN; n += MR) V[cur][sub][n] = rsh[sub][n];
            __syncthreads();
        }
    }

    // Final posterior lives in buffer ITERS%2 = 1.
    float* ob = out + b * NN;
    #pragma unroll
    for (int n = row; n < NN; n += MR) ob[n] = V[1][sub][n];
}

extern "C" void kernel_launch(void* const* d_in, const int* in_sizes, int n_in,
                              void* d_out, int out_size) {
    const float* r     = (const float*)d_in[0];   // (256, 576)
    const float* H     = (const float*)d_in[1];   // (144, 576)
    const float* alpha = (const float*)d_in[2];   // (3,)
    const float* beta  = (const float*)d_in[3];   // (3,)
    float* out = (float*)d_out;                   // (256, 576)

    ldpc_prep_kernel<<<MR, 32>>>(H);
    ldpc_decode_kernel<<<BATCH / SUBS, TPB>>>(r, alpha, beta, out);
}